// round 6
// baseline (speedup 1.0000x reference)
#include <cuda_runtime.h>
#include <cuda_bf16.h>
#include <cstdint>

#define NN 131072
#define NE 4194304
#define FI 64

// ---------------- scratch (device globals: no allocation allowed) ----------
__device__ float g_deg [NN];         // degree, then dinv in-place
__device__ int   g_cnt [NN];         // in-degree histogram (by dst)
__device__ int   g_off [NN + 1];     // CSR row offsets (by dst)
__device__ int   g_cur [NN];         // scatter cursors
__device__ int2  g_edge[NE];         // CSR record: {src, weight-bits}
__device__ float g_T1[NN * FI];      // Tx1 = spmm(x)
__device__ float g_T2[NN * FI];      // Tx2 = 2*spmm(Tx1) - x
__device__ float g_T3[NN * FI];      // Tx3 = 2*spmm(Tx2) - Tx1
// B operand [chunk kb][n 0..255][k 0..63] bf16, SW128-pre-swizzled (32KB/chunk)
__device__ __nv_bfloat16 g_Bhi[4 * 256 * 64];
__device__ __nv_bfloat16 g_Blo[4 * 256 * 64];
__device__ float g_bias[256];        // b_x[g]+b_h[g] for gate0|gate2
__device__ int   g_any;              // detector: any odd word nonzero?
__device__ int   g_is64;             // 1 if edge_index is int64

// ---------------- edge-index access (dtype-robust, trap-proof) -------------
__device__ __forceinline__ int eidx(const void* ei, unsigned i) {
    int v;
    if (g_is64) v = (int)((const long long*)ei)[i];
    else        v = ((const int*)ei)[i];
    return v & (NN - 1);             // NN = 2^17: no-op for valid ids, trap-proof
}

// ---------------- helpers ----------------------------------------------------
__device__ __forceinline__ uint32_t smem_u32(const void* p) {
    uint32_t a;
    asm("{ .reg .u64 t; cvta.to.shared.u64 t, %1; cvt.u32.u64 %0, t; }"
        : "=r"(a) : "l"(p));
    return a;
}
#define SWZ128(o) ((o) ^ (((o) >> 3) & 0x70))

__device__ __forceinline__ void ldsm4(uint32_t& r0, uint32_t& r1, uint32_t& r2,
                                      uint32_t& r3, uint32_t addr) {
    asm volatile("ldmatrix.sync.aligned.m8n8.x4.shared.b16 {%0,%1,%2,%3}, [%4];"
                 : "=r"(r0), "=r"(r1), "=r"(r2), "=r"(r3) : "r"(addr));
}
__device__ __forceinline__ void mma16816(float* c, const uint32_t* a,
                                         uint32_t b0, uint32_t b1) {
    asm volatile("mma.sync.aligned.m16n8k16.row.col.f32.bf16.bf16.f32 "
                 "{%0,%1,%2,%3}, {%4,%5,%6,%7}, {%8,%9}, {%0,%1,%2,%3};"
                 : "+f"(c[0]), "+f"(c[1]), "+f"(c[2]), "+f"(c[3])
                 : "r"(a[0]), "r"(a[1]), "r"(a[2]), "r"(a[3]), "r"(b0), "r"(b1));
}
__device__ __forceinline__ float gru_h(float u, float v) {
    float z  = __fdividef(1.f, 1.f + __expf(-u));             // sigmoid
    float th = 1.f - __fdividef(2.f, __expf(2.f * v) + 1.f);  // tanh, inf-safe
    return fmaxf((1.f - z) * th, 0.f);                        // relu((1-z)*tanh)
}
__device__ __forceinline__ void fma4(float4& a, float w, float4 v) {
    a.x = fmaf(w, v.x, a.x); a.y = fmaf(w, v.y, a.y);
    a.z = fmaf(w, v.z, a.z); a.w = fmaf(w, v.w, a.w);
}

// ---------------- prep kernels ---------------------------------------------
// sample odd 32-bit words of the first 2*NE words: all-zero <=> int64 layout
__global__ void k_detect(const int* __restrict__ w) {
    int t = blockIdx.x * 256 + threadIdx.x;      // 4096 samples
    int stride = (2 * (NE / 4096));
    int v = w[(unsigned)(t * stride + 1)];
    if (__syncthreads_or(v != 0) && threadIdx.x == 0) atomicOr(&g_any, 1);
}
__global__ void k_setflag() { g_is64 = (g_any == 0); }

__global__ void k_deg(const void* __restrict__ ei, const float* __restrict__ ew) {
    unsigned e = blockIdx.x * 256 + threadIdx.x;
    if (e >= NE) return;
    atomicAdd(&g_deg[eidx(ei, e)], ew[e]);
    atomicAdd(&g_cnt[eidx(ei, NE + e)], 1);
}

__global__ void k_dinv() {
    int i = blockIdx.x * 256 + threadIdx.x;
    if (i < NN) {
        float d = g_deg[i];
        g_deg[i] = (d > 0.f) ? rsqrtf(d) : 0.f;
    }
}

// single-block exclusive scan of g_cnt -> g_off, g_cur  (1024 threads)
__global__ void k_scan() {
    __shared__ int wsum[32];
    __shared__ int carry_s;
    const int tid  = threadIdx.x;
    const int lane = tid & 31;
    const int w    = tid >> 5;
    int carry = 0;
    for (int base = 0; base < NN; base += 1024) {
        int v = g_cnt[base + tid];
        int x = v;
#pragma unroll
        for (int d = 1; d < 32; d <<= 1) {
            int y = __shfl_up_sync(0xffffffffu, x, d);
            if (lane >= d) x += y;
        }
        if (lane == 31) wsum[w] = x;
        __syncthreads();
        if (w == 0) {
            int s = wsum[lane];
#pragma unroll
            for (int d = 1; d < 32; d <<= 1) {
                int y = __shfl_up_sync(0xffffffffu, s, d);
                if (lane >= d) s += y;
            }
            wsum[lane] = s;
        }
        __syncthreads();
        int incl = x + (w > 0 ? wsum[w - 1] : 0) + carry;
        int excl = incl - v;
        g_off[base + tid] = excl;
        g_cur[base + tid] = excl;
        if (tid == 1023) carry_s = incl;
        __syncthreads();
        carry = carry_s;
        __syncthreads();
    }
    if (tid == 0) g_off[NN] = carry;
}

// scatter edges into packed CSR records (one int atomic + one 8B store/edge)
__global__ void k_scatter(const void* __restrict__ ei, const float* __restrict__ ew) {
    unsigned e = blockIdx.x * 256 + threadIdx.x;
    if (e >= NE) return;
    int s = eidx(ei, e);
    int d = eidx(ei, NE + e);
    float w = -g_deg[s] * ew[e] * g_deg[d];
    int pos = atomicAdd(&g_cur[d], 1);
    if (pos < NE) g_edge[pos] = make_int2(s, __float_as_int(w));
}

// Pack B for MMA: B_mma[n][k] = W[k][n]; split hi/lo bf16; SW128-pre-swizzled.
__global__ void k_pack(const float* __restrict__ Wx, const float* __restrict__ bx,
                       const float* __restrict__ bh) {
    int i = blockIdx.x * 256 + threadIdx.x;   // 65536 total
    int kb = i >> 14, n = (i >> 6) & 255, kk = i & 63;
    int g  = (n < 128) ? 0 : 2;
    int jj = n & 127;
    float w = Wx[(((size_t)(g * 4 + kb) * 64 + kk) * 128) + jj];
    __nv_bfloat16 hi = __float2bfloat16(w);
    __nv_bfloat16 lo = __float2bfloat16(w - __bfloat162float(hi));
    uint32_t off = SWZ128((uint32_t)(n * 128 + kk * 2));   // byte off in 32KB tile
    uint32_t idx = (uint32_t)kb * 16384 + (off >> 1);
    g_Bhi[idx] = hi;
    g_Blo[idx] = lo;
    if (kb == 0 && kk == 0) g_bias[n] = bx[g * 128 + jj] + bh[g * 128 + jj];
}

// ---------------- SpMM gather: out[d] = CHEB ? (2*sum - prev[d]) : sum ------
// One warp per dst node; 2 half-warps × unroll-4 = 8 edges in flight.
template <bool CHEB>
__global__ void __launch_bounds__(256)
k_spmm(const float4* __restrict__ vin, const float4* __restrict__ prev,
       float4* __restrict__ vout) {
    const int node = blockIdx.x * 8 + (threadIdx.x >> 5);
    const int lane = threadIdx.x & 31;
    const int lh   = lane & 15;
    const int half = lane >> 4;
    const int beg = g_off[node];
    const int end = g_off[node + 1];

    float4 acc = make_float4(0.f, 0.f, 0.f, 0.f);
    int i = beg + half;
    for (; i + 6 < end; i += 8) {        // 4 edges per half-warp in flight
        int2 e0 = g_edge[i];
        int2 e1 = g_edge[i + 2];
        int2 e2 = g_edge[i + 4];
        int2 e3 = g_edge[i + 6];
        float4 v0 = vin[(long)e0.x * 16 + lh];
        float4 v1 = vin[(long)e1.x * 16 + lh];
        float4 v2 = vin[(long)e2.x * 16 + lh];
        float4 v3 = vin[(long)e3.x * 16 + lh];
        fma4(acc, __int_as_float(e0.y), v0);
        fma4(acc, __int_as_float(e1.y), v1);
        fma4(acc, __int_as_float(e2.y), v2);
        fma4(acc, __int_as_float(e3.y), v3);
    }
    for (; i < end; i += 2) {
        int2 e0 = g_edge[i];
        float4 v0 = vin[(long)e0.x * 16 + lh];
        fma4(acc, __int_as_float(e0.y), v0);
    }
    acc.x += __shfl_xor_sync(0xffffffffu, acc.x, 16);
    acc.y += __shfl_xor_sync(0xffffffffu, acc.y, 16);
    acc.z += __shfl_xor_sync(0xffffffffu, acc.z, 16);
    acc.w += __shfl_xor_sync(0xffffffffu, acc.w, 16);

    if (half == 0) {
        float4 r;
        if (CHEB) {
            float4 p = prev[(long)node * 16 + lh];
            r.x = 2.f * acc.x - p.x; r.y = 2.f * acc.y - p.y;
            r.z = 2.f * acc.z - p.z; r.w = 2.f * acc.w - p.w;
        } else {
            r = acc;
        }
        vout[(long)node * 16 + lh] = r;
    }
}

// ---------------- mma.sync GEMM [128 rows/CTA, N=256, K=256] + GRU epilogue -
// D = Ah*Bh + Al*Bh + Ah*Bl (bf16x3 split), fp32 accum in registers.
// SMEM (dynamic): [0..1024) row-reduce buffers; Ahi@1024 (16KB); Alo@17408;
//                 Bhi@33792 (32KB); Blo@66560 (32KB). Total 99328 B.
#define SM_AHI 1024
#define SM_ALO 17408
#define SM_BHI 33792
#define SM_BLO 66560
#define SM_DYN 99328

__global__ void __launch_bounds__(256, 1)
k_gemm_mma(const float* __restrict__ x, const float* __restrict__ Wlin,
           const float* __restrict__ blin, float* __restrict__ outbuf) {
    extern __shared__ char smem[];
    float* smf = (float*)smem;               // [0..128) rs, [128..256) dt
    const uint32_t sb  = smem_u32(smem);
    const int tid  = threadIdx.x;
    const int wid  = tid >> 5;
    const int lane = tid & 31;
    const int wm   = wid & 3;                // m quarter: rows wm*32..+31
    const int wn   = wid >> 2;               // n half pattern
    const long rowBase = (long)blockIdx.x * 128;

    if (tid < 128) { smf[tid] = 0.f; smf[128 + tid] = 0.f; }

    const float* bases[4] = { x    + rowBase * FI, g_T1 + rowBase * FI,
                              g_T2 + rowBase * FI, g_T3 + rowBase * FI };

    float acc[2][16][4];
#pragma unroll
    for (int mt = 0; mt < 2; mt++)
#pragma unroll
        for (int t = 0; t < 16; t++)
#pragma unroll
            for (int q = 0; q < 4; q++) acc[mt][t][q] = 0.f;

#pragma unroll 1
    for (int c = 0; c < 4; c++) {
        // --- stage A chunk: 128x64 fp32 -> hi/lo bf16, SW128 swizzled
        const float4* Asrc = (const float4*)bases[c];
#pragma unroll
        for (int it = 0; it < 8; it++) {
            int idx = tid + it * 256;           // 2048 float4
            int r  = idx >> 4;
            int c4 = idx & 15;
            float4 v = Asrc[r * 16 + c4];
            __nv_bfloat16 h0 = __float2bfloat16(v.x);
            __nv_bfloat16 h1 = __float2bfloat16(v.y);
            __nv_bfloat16 h2 = __float2bfloat16(v.z);
            __nv_bfloat16 h3 = __float2bfloat16(v.w);
            __nv_bfloat16 l0 = __float2bfloat16(v.x - __bfloat162float(h0));
            __nv_bfloat16 l1 = __float2bfloat16(v.y - __bfloat162float(h1));
            __nv_bfloat16 l2 = __float2bfloat16(v.z - __bfloat162float(h2));
            __nv_bfloat16 l3 = __float2bfloat16(v.w - __bfloat162float(h3));
            uint32_t off = SWZ128((uint32_t)(r * 128 + c4 * 8));
            *(__nv_bfloat162*)(smem + SM_AHI + off)     = __nv_bfloat162(h0, h1);
            *(__nv_bfloat162*)(smem + SM_AHI + off + 4) = __nv_bfloat162(h2, h3);
            *(__nv_bfloat162*)(smem + SM_ALO + off)     = __nv_bfloat162(l0, l1);
            *(__nv_bfloat162*)(smem + SM_ALO + off + 4) = __nv_bfloat162(l2, l3);
        }
        // --- stage B chunk: straight uint4 copy (pre-swizzled in global)
        const uint4* bh_src = (const uint4*)(g_Bhi + (size_t)c * 16384);
        const uint4* bl_src = (const uint4*)(g_Blo + (size_t)c * 16384);
#pragma unroll
        for (int it = 0; it < 8; it++) {
            int idx = tid + it * 256;           // 2048 uint4
            ((uint4*)(smem + SM_BHI))[idx] = bh_src[idx];
            ((uint4*)(smem + SM_BLO))[idx] = bl_src[idx];
        }
        __syncthreads();

        // --- MMA core: 3 split-combos × 4 k16-steps × (2 m-tiles × 16 n-tiles)
#pragma unroll 1
        for (int sp = 0; sp < 3; sp++) {
            const uint32_t Aoff = (sp == 1) ? SM_ALO : SM_AHI;
            const uint32_t Boff = (sp == 2) ? SM_BLO : SM_BHI;
#pragma unroll
            for (int ks = 0; ks < 4; ks++) {
                uint32_t a[2][4];
#pragma unroll
                for (int mt = 0; mt < 2; mt++) {
                    int r = wm * 32 + mt * 16 + (lane & 15);
                    int g = 2 * ks + (lane >> 4);
                    uint32_t ad = sb + Aoff + (uint32_t)(r * 128 + ((g ^ (r & 7)) << 4));
                    ldsm4(a[mt][0], a[mt][1], a[mt][2], a[mt][3], ad);
                }
#pragma unroll
                for (int p = 0; p < 8; p++) {
                    int tix = (p < 4) ? (2 * p) : (8 + 2 * (p - 4));
                    int ntb = wn * 8 + ((p < 4) ? (2 * p) : (16 + 2 * (p - 4)));
                    int n = ntb * 8 + (lane & 7) + ((lane >> 4) << 3);
                    int g = 2 * ks + ((lane >> 3) & 1);
                    uint32_t bd = sb + Boff + (uint32_t)(n * 128 + ((g ^ (n & 7)) << 4));
                    uint32_t b0, b1, b2, b3;
                    ldsm4(b0, b1, b2, b3, bd);
                    mma16816(acc[0][tix],     a[0], b0, b1);
                    mma16816(acc[1][tix],     a[1], b0, b1);
                    mma16816(acc[0][tix + 1], a[0], b2, b3);
                    mma16816(acc[1][tix + 1], a[1], b2, b3);
                }
            }
        }
        __syncthreads();
    }

    // ---- GRU epilogue on register accumulators -----------------------------
    const float bl = __ldg(blin);
#pragma unroll
    for (int mt = 0; mt < 2; mt++) {
        float rs0 = 0.f, dt0 = 0.f, rs1 = 0.f, dt1 = 0.f;
#pragma unroll
        for (int i = 0; i < 8; i++) {
            int j0 = wn * 64 + i * 8 + 2 * (lane & 3);
            float bu0 = __ldg(g_bias + j0),       bu1 = __ldg(g_bias + j0 + 1);
            float bv0 = __ldg(g_bias + j0 + 128), bv1 = __ldg(g_bias + j0 + 129);
            float w0  = __ldg(Wlin + j0),         w1  = __ldg(Wlin + j0 + 1);
            float h00 = gru_h(acc[mt][i][0] + bu0, acc[mt][8 + i][0] + bv0);
            float h01 = gru_h(acc[mt][i][1] + bu1, acc[mt][8 + i][1] + bv1);
            float h10 = gru_h(acc[mt][i][2] + bu0, acc[mt][8 + i][2] + bv0);
            float h11 = gru_h(acc[mt][i][3] + bu1, acc[mt][8 + i][3] + bv1);
            rs0 += h00 + h01; dt0 = fmaf(h00, w0, fmaf(h01, w1, dt0));
            rs1 += h10 + h11; dt1 = fmaf(h10, w0, fmaf(h11, w1, dt1));
        }
#pragma unroll
        for (int s = 1; s < 4; s <<= 1) {
            rs0 += __shfl_xor_sync(0xffffffffu, rs0, s);
            dt0 += __shfl_xor_sync(0xffffffffu, dt0, s);
            rs1 += __shfl_xor_sync(0xffffffffu, rs1, s);
            dt1 += __shfl_xor_sync(0xffffffffu, dt1, s);
        }
        if ((lane & 3) == 0) {
            int r = wm * 32 + mt * 16 + (lane >> 2);
            atomicAdd(&smf[r],           rs0);
            atomicAdd(&smf[128 + r],     dt0);
            atomicAdd(&smf[r + 8],       rs1);
            atomicAdd(&smf[128 + r + 8], dt1);
        }
    }
    __syncthreads();
    if (tid < 128) {
        long grow = rowBase + tid;
        outbuf[grow]      = smf[128 + tid] + bl;   // out = h @ W_lin + b_lin
        outbuf[NN + grow] = sqrtf(smf[tid]);       // logits = sqrt(rowsum(relu(H)))
    }
}

// ---------------- launch orchestration -------------------------------------
extern "C" void kernel_launch(void* const* d_in, const int* in_sizes, int n_in,
                              void* d_out, int out_size) {
    const float* x  = (const float*)d_in[0];
    const void*  ei = d_in[1];                 // int32 or int64 — detected on device
    const float* ew = (const float*)d_in[2];
    const float* Wx = (const float*)d_in[3];
    // d_in[4] = W_h : provably unused (H==0 => cheb(H,*) == bias)
    const float* bx = (const float*)d_in[5];
    const float* bh = (const float*)d_in[6];
    const float* Wl = (const float*)d_in[7];
    const float* bl = (const float*)d_in[8];
    float* out = (float*)d_out;
    (void)in_sizes; (void)n_in; (void)out_size;

    void *pT1, *pT2, *pT3, *pdeg, *pcnt, *pany;
    cudaGetSymbolAddress(&pT1, g_T1);
    cudaGetSymbolAddress(&pT2, g_T2);
    cudaGetSymbolAddress(&pT3, g_T3);
    cudaGetSymbolAddress(&pdeg, g_deg);
    cudaGetSymbolAddress(&pcnt, g_cnt);
    cudaGetSymbolAddress(&pany, g_any);

    cudaFuncSetAttribute(k_gemm_mma, cudaFuncAttributeMaxDynamicSharedMemorySize, SM_DYN);

    // ---- prep: detect dtype -> degree/hist -> dinv -> scan -> scatter -> pack
    cudaMemsetAsync(pdeg, 0, (size_t)NN * sizeof(float));
    cudaMemsetAsync(pcnt, 0, (size_t)NN * sizeof(int));
    cudaMemsetAsync(pany, 0, sizeof(int));
    k_detect <<<16, 256>>>((const int*)ei);
    k_setflag<<<1, 1>>>();
    k_deg    <<<NE / 256, 256>>>(ei, ew);
    k_dinv   <<<NN / 256, 256>>>();
    k_scan   <<<1, 1024>>>();
    k_scatter<<<NE / 256, 256>>>(ei, ew);
    k_pack   <<<256, 256>>>(Wx, bx, bh);

    // ---- Chebyshev: T1 = L x ; T2 = 2 L T1 - x ; T3 = 2 L T2 - T1
    k_spmm<false><<<NN / 8, 256>>>((const float4*)x, nullptr, (float4*)pT1);
    k_spmm<true> <<<NN / 8, 256>>>((const float4*)pT1, (const float4*)x,  (float4*)pT2);
    k_spmm<true> <<<NN / 8, 256>>>((const float4*)pT2, (const float4*)pT1, (float4*)pT3);

    // ---- fused mma.sync GEMM + GRU + head
    k_gemm_mma<<<NN / 128, 256, SM_DYN>>>(x, Wl, bl, out);
}

// round 7
// speedup vs baseline: 1.3282x; 1.3282x over previous
#include <cuda_runtime.h>
#include <cuda_fp16.h>
#include <cstdint>

#define NN 131072
#define NE 4194304
#define FI 64

// ---------------- scratch (device globals: no allocation allowed) ----------
__device__ float  g_deg [NN];        // degree, then dinv in-place
__device__ int    g_cnt [NN];        // in-degree histogram (by dst)
__device__ int    g_off [NN + 1];    // CSR row offsets (by dst)
__device__ int    g_rank[NE];        // per-edge rank within its dst row
__device__ int2   g_edge[NE];        // CSR record: {src, weight-bits}
__device__ __half g_xh[NN * FI];     // x cast to fp16
__device__ __half g_Y1[NN * FI];     // Y1 = L x
__device__ __half g_Y2[NN * FI];     // Y2 = L Y1
__device__ __half g_Y3[NN * FI];     // Y3 = L Y2
// B operand [chunk kb][n 0..255][k 0..63] fp16, SW128-pre-swizzled (16KB/chunk)
__device__ __half g_Bhi[4 * 256 * 64];
__device__ __half g_Blo[4 * 256 * 64];
__device__ float  g_bias[256];       // b_x[g]+b_h[g] for gate0|gate2
__device__ int    g_any;             // detector: any odd word nonzero?
__device__ int    g_is64;            // 1 if edge_index is int64

// ---------------- edge-index access (dtype-robust, trap-proof) -------------
__device__ __forceinline__ int eidx(const void* ei, unsigned i) {
    int v;
    if (g_is64) v = (int)((const long long*)ei)[i];
    else        v = ((const int*)ei)[i];
    return v & (NN - 1);             // NN = 2^17: no-op for valid ids, trap-proof
}

// ---------------- helpers ----------------------------------------------------
__device__ __forceinline__ uint32_t smem_u32(const void* p) {
    uint32_t a;
    asm("{ .reg .u64 t; cvta.to.shared.u64 t, %1; cvt.u32.u64 %0, t; }"
        : "=r"(a) : "l"(p));
    return a;
}
#define SWZ128(o) ((o) ^ (((o) >> 3) & 0x70))

__device__ __forceinline__ void ldsm4(uint32_t& r0, uint32_t& r1, uint32_t& r2,
                                      uint32_t& r3, uint32_t addr) {
    asm volatile("ldmatrix.sync.aligned.m8n8.x4.shared.b16 {%0,%1,%2,%3}, [%4];"
                 : "=r"(r0), "=r"(r1), "=r"(r2), "=r"(r3) : "r"(addr));
}
__device__ __forceinline__ void mma16816(float* c, const uint32_t* a,
                                         uint32_t b0, uint32_t b1) {
    asm volatile("mma.sync.aligned.m16n8k16.row.col.f32.f16.f16.f32 "
                 "{%0,%1,%2,%3}, {%4,%5,%6,%7}, {%8,%9}, {%0,%1,%2,%3};"
                 : "+f"(c[0]), "+f"(c[1]), "+f"(c[2]), "+f"(c[3])
                 : "r"(a[0]), "r"(a[1]), "r"(a[2]), "r"(a[3]), "r"(b0), "r"(b1));
}
__device__ __forceinline__ float gru_h(float u, float v) {
    float z  = __fdividef(1.f, 1.f + __expf(-u));             // sigmoid
    float th = 1.f - __fdividef(2.f, __expf(2.f * v) + 1.f);  // tanh, inf-safe
    return fmaxf((1.f - z) * th, 0.f);                        // relu((1-z)*tanh)
}

// ---------------- prep kernels ---------------------------------------------
// sample odd 32-bit words of the first 2*NE words: all-zero <=> int64 layout
__global__ void k_detect(const int* __restrict__ w) {
    int t = blockIdx.x * 256 + threadIdx.x;      // 4096 samples
    int stride = (2 * (NE / 4096));
    int v = w[(unsigned)(t * stride + 1)];
    if (__syncthreads_or(v != 0) && threadIdx.x == 0) atomicOr(&g_any, 1);
}
__global__ void k_setflag() { g_is64 = (g_any == 0); }

// x -> fp16 cast (independent of edge prep)
__global__ void k_xcast(const float4* __restrict__ x) {
    int i = blockIdx.x * 256 + threadIdx.x;      // NN*FI/4 threads
    float4 v = x[i];
    __half2 a = __floats2half2_rn(v.x, v.y);
    __half2 b = __floats2half2_rn(v.z, v.w);
    uint2 o;
    o.x = *reinterpret_cast<uint32_t*>(&a);
    o.y = *reinterpret_cast<uint32_t*>(&b);
    *reinterpret_cast<uint2*>(g_xh + (size_t)i * 4) = o;
}

// weighted degree (by src) + in-degree histogram (by dst); the histogram
// atomic's return value IS the CSR rank -> saved for atomic-free scatter
__global__ void k_deg(const void* __restrict__ ei, const float* __restrict__ ew) {
    unsigned e = blockIdx.x * 256 + threadIdx.x;
    if (e >= NE) return;
    atomicAdd(&g_deg[eidx(ei, e)], ew[e]);
    g_rank[e] = atomicAdd(&g_cnt[eidx(ei, NE + e)], 1);
}

__global__ void k_dinv() {
    int i = blockIdx.x * 256 + threadIdx.x;
    if (i < NN) {
        float d = g_deg[i];
        g_deg[i] = (d > 0.f) ? rsqrtf(d) : 0.f;
    }
}

// single-block exclusive scan of g_cnt -> g_off  (1024 threads)
__global__ void k_scan() {
    __shared__ int wsum[32];
    __shared__ int carry_s;
    const int tid  = threadIdx.x;
    const int lane = tid & 31;
    const int w    = tid >> 5;
    int carry = 0;
    for (int base = 0; base < NN; base += 1024) {
        int v = g_cnt[base + tid];
        int x = v;
#pragma unroll
        for (int d = 1; d < 32; d <<= 1) {
            int y = __shfl_up_sync(0xffffffffu, x, d);
            if (lane >= d) x += y;
        }
        if (lane == 31) wsum[w] = x;
        __syncthreads();
        if (w == 0) {
            int s = wsum[lane];
#pragma unroll
            for (int d = 1; d < 32; d <<= 1) {
                int y = __shfl_up_sync(0xffffffffu, s, d);
                if (lane >= d) s += y;
            }
            wsum[lane] = s;
        }
        __syncthreads();
        int incl = x + (w > 0 ? wsum[w - 1] : 0) + carry;
        g_off[base + tid] = incl - v;
        if (tid == 1023) carry_s = incl;
        __syncthreads();
        carry = carry_s;
        __syncthreads();
    }
    if (tid == 0) g_off[NN] = carry;
}

// scatter edges into packed CSR records — NO atomics (rank precomputed)
__global__ void k_scatter(const void* __restrict__ ei, const float* __restrict__ ew) {
    unsigned e = blockIdx.x * 256 + threadIdx.x;
    if (e >= NE) return;
    int s = eidx(ei, e);
    int d = eidx(ei, NE + e);
    float w = -g_deg[s] * ew[e] * g_deg[d];
    unsigned pos = (unsigned)(g_off[d] + g_rank[e]) & (NE - 1);  // trap-proof
    g_edge[pos] = make_int2(s, __float_as_int(w));
}

// Pack B: reparametrized Chebyshev weights (Y_k = L^k x basis), transposed
// [n][k], split fp16 hi/lo, SW128-pre-swizzled.
//   B0 = W0 - W2 ; B1 = W1 - 3*W3 ; B2 = 2*W2 ; B3 = 4*W3
__global__ void k_pack(const float* __restrict__ Wx, const float* __restrict__ bx,
                       const float* __restrict__ bh) {
    int i = blockIdx.x * 256 + threadIdx.x;   // 65536 total
    int kb = i >> 14, n = (i >> 6) & 255, kk = i & 63;
    int g  = (n < 128) ? 0 : 2;
    int jj = n & 127;
    const size_t base = (size_t)g * 4 * 64 * 128 + (size_t)kk * 128 + jj;
    const size_t kstep = (size_t)64 * 128;
    float w;
    if      (kb == 0) w = Wx[base]             - Wx[base + 2 * kstep];
    else if (kb == 1) w = Wx[base + kstep]     - 3.f * Wx[base + 3 * kstep];
    else if (kb == 2) w = 2.f * Wx[base + 2 * kstep];
    else              w = 4.f * Wx[base + 3 * kstep];
    __half hi = __float2half(w);
    __half lo = __float2half(w - __half2float(hi));
    uint32_t off = SWZ128((uint32_t)(n * 128 + kk * 2));   // byte off in 32KB tile
    uint32_t idx = (uint32_t)kb * 16384 + (off >> 1);
    g_Bhi[idx] = hi;
    g_Blo[idx] = lo;
    if (kb == 0 && kk == 0) g_bias[n] = bx[g * 128 + jj] + bh[g * 128 + jj];
}

// ---------------- SpMM gather (fp16 rows): out[d] = sum_e w_e * vin[src_e] --
// One warp per dst node; 16 lanes/row (8B = 4 halves each), 2 edges in flight.
__global__ void __launch_bounds__(256)
k_spmm(const uint2* __restrict__ vin, uint2* __restrict__ vout) {
    const int node = blockIdx.x * 8 + (threadIdx.x >> 5);
    const int lane = threadIdx.x & 31;
    const int lh   = lane & 15;
    const int half = lane >> 4;
    const int beg = g_off[node];
    const int end = g_off[node + 1];

    float4 acc = make_float4(0.f, 0.f, 0.f, 0.f);
    int i = beg + half;
    for (; i + 2 < end; i += 4) {
        int2 e0 = g_edge[i];
        int2 e1 = g_edge[i + 2];
        uint2 u0 = vin[(long)e0.x * 16 + lh];
        uint2 u1 = vin[(long)e1.x * 16 + lh];
        float w0 = __int_as_float(e0.y);
        float w1 = __int_as_float(e1.y);
        float2 f0 = __half22float2(*reinterpret_cast<__half2*>(&u0.x));
        float2 f1 = __half22float2(*reinterpret_cast<__half2*>(&u0.y));
        float2 f2 = __half22float2(*reinterpret_cast<__half2*>(&u1.x));
        float2 f3 = __half22float2(*reinterpret_cast<__half2*>(&u1.y));
        acc.x = fmaf(w0, f0.x, acc.x); acc.y = fmaf(w0, f0.y, acc.y);
        acc.z = fmaf(w0, f1.x, acc.z); acc.w = fmaf(w0, f1.y, acc.w);
        acc.x = fmaf(w1, f2.x, acc.x); acc.y = fmaf(w1, f2.y, acc.y);
        acc.z = fmaf(w1, f3.x, acc.z); acc.w = fmaf(w1, f3.y, acc.w);
    }
    if (i < end) {
        int2 e0 = g_edge[i];
        uint2 u0 = vin[(long)e0.x * 16 + lh];
        float w0 = __int_as_float(e0.y);
        float2 f0 = __half22float2(*reinterpret_cast<__half2*>(&u0.x));
        float2 f1 = __half22float2(*reinterpret_cast<__half2*>(&u0.y));
        acc.x = fmaf(w0, f0.x, acc.x); acc.y = fmaf(w0, f0.y, acc.y);
        acc.z = fmaf(w0, f1.x, acc.z); acc.w = fmaf(w0, f1.y, acc.w);
    }
    acc.x += __shfl_xor_sync(0xffffffffu, acc.x, 16);
    acc.y += __shfl_xor_sync(0xffffffffu, acc.y, 16);
    acc.z += __shfl_xor_sync(0xffffffffu, acc.z, 16);
    acc.w += __shfl_xor_sync(0xffffffffu, acc.w, 16);

    if (half == 0) {
        __half2 h01 = __floats2half2_rn(acc.x, acc.y);
        __half2 h23 = __floats2half2_rn(acc.z, acc.w);
        uint2 o;
        o.x = *reinterpret_cast<uint32_t*>(&h01);
        o.y = *reinterpret_cast<uint32_t*>(&h23);
        vout[(long)node * 16 + lh] = o;
    }
}

// ---------------- mma.sync GEMM [128 rows/CTA, N=256, K=256] + GRU epilogue -
// D = A*Bhi + A*Blo (A fp16 as stored; B fp16 hi/lo split), fp32 accum.
// SMEM (dynamic): [0..1024) row-reduce; A@1024 (16KB); Bhi@17408 (32KB);
//                 Blo@50176 (32KB). Total 82944 B.
#define SM_A   1024
#define SM_BHI 17408
#define SM_BLO 50176
#define SM_DYN 82944

__global__ void __launch_bounds__(256, 1)
k_gemm_mma(const float* __restrict__ Wlin, const float* __restrict__ blin,
           float* __restrict__ outbuf) {
    extern __shared__ char smem[];
    float* smf = (float*)smem;               // [0..128) rs, [128..256) dt
    const uint32_t sb  = smem_u32(smem);
    const int tid  = threadIdx.x;
    const int wid  = tid >> 5;
    const int lane = tid & 31;
    const int wm   = wid & 3;                // m quarter: rows wm*32..+31
    const int wn   = wid >> 2;               // n half pattern
    const long rowBase = (long)blockIdx.x * 128;

    if (tid < 128) { smf[tid] = 0.f; smf[128 + tid] = 0.f; }

    const __half* bases[4] = { g_xh + rowBase * FI, g_Y1 + rowBase * FI,
                               g_Y2 + rowBase * FI, g_Y3 + rowBase * FI };

    float acc[2][16][4];
#pragma unroll
    for (int mt = 0; mt < 2; mt++)
#pragma unroll
        for (int t = 0; t < 16; t++)
#pragma unroll
            for (int q = 0; q < 4; q++) acc[mt][t][q] = 0.f;

#pragma unroll 1
    for (int c = 0; c < 4; c++) {
        // --- stage A chunk: 128 rows x 64 fp16 (128B/row), SW128 swizzled
        const uint4* Asrc = (const uint4*)bases[c];
#pragma unroll
        for (int it = 0; it < 4; it++) {
            int idx = tid + it * 256;           // 1024 uint4
            int r  = idx >> 3;
            int c8 = idx & 7;
            uint4 v = Asrc[r * 8 + c8];
            *(uint4*)(smem + SM_A + r * 128 + ((c8 ^ (r & 7)) << 4)) = v;
        }
        // --- stage B chunk: straight uint4 copy (pre-swizzled in global)
        const uint4* bh_src = (const uint4*)(g_Bhi + (size_t)c * 16384);
        const uint4* bl_src = (const uint4*)(g_Blo + (size_t)c * 16384);
#pragma unroll
        for (int it = 0; it < 8; it++) {
            int idx = tid + it * 256;           // 2048 uint4
            ((uint4*)(smem + SM_BHI))[idx] = bh_src[idx];
            ((uint4*)(smem + SM_BLO))[idx] = bl_src[idx];
        }
        __syncthreads();

        // --- MMA core: 2 B-splits × 4 k16-steps × (2 m-tiles × 16 n-tiles)
#pragma unroll 1
        for (int sp = 0; sp < 2; sp++) {
            const uint32_t Boff = (sp == 1) ? SM_BLO : SM_BHI;
#pragma unroll
            for (int ks = 0; ks < 4; ks++) {
                uint32_t a[2][4];
#pragma unroll
                for (int mt = 0; mt < 2; mt++) {
                    int r = wm * 32 + mt * 16 + (lane & 15);
                    int g = 2 * ks + (lane >> 4);
                    uint32_t ad = sb + SM_A + (uint32_t)(r * 128 + ((g ^ (r & 7)) << 4));
                    ldsm4(a[mt][0], a[mt][1], a[mt][2], a[mt][3], ad);
                }
#pragma unroll
                for (int p = 0; p < 8; p++) {
                    int tix = (p < 4) ? (2 * p) : (8 + 2 * (p - 4));
                    int ntb = wn * 8 + ((p < 4) ? (2 * p) : (16 + 2 * (p - 4)));
                    int n = ntb * 8 + (lane & 7) + ((lane >> 4) << 3);
                    int g = 2 * ks + ((lane >> 3) & 1);
                    uint32_t bd = sb + Boff + (uint32_t)(n * 128 + ((g ^ (n & 7)) << 4));
                    uint32_t b0, b1, b2, b3;
                    ldsm4(b0, b1, b2, b3, bd);
                    mma16816(acc[0][tix],     a[0], b0, b1);
                    mma16816(acc[1][tix],     a[1], b0, b1);
                    mma16816(acc[0][tix + 1], a[0], b2, b3);
                    mma16816(acc[1][tix + 1], a[1], b2, b3);
                }
            }
        }
        __syncthreads();
    }

    // ---- GRU epilogue on register accumulators -----------------------------
    const float bl = __ldg(blin);
#pragma unroll
    for (int mt = 0; mt < 2; mt++) {
        float rs0 = 0.f, dt0 = 0.f, rs1 = 0.f, dt1 = 0.f;
#pragma unroll
        for (int i = 0; i < 8; i++) {
            int j0 = wn * 64 + i * 8 + 2 * (lane & 3);
            float bu0 = __ldg(g_bias + j0),       bu1 = __ldg(g_bias + j0 + 1);
            float bv0 = __ldg(g_bias + j0 + 128), bv1 = __ldg(g_bias + j0 + 129);
            float w0  = __ldg(Wlin + j0),         w1  = __ldg(Wlin + j0 + 1);
            float h00 = gru_h(acc[mt][i][0] + bu0, acc[mt][8 + i][0] + bv0);
            float h01 = gru_h(acc[mt][i][1] + bu1, acc[mt][8 + i][1] + bv1);
            float h10 = gru_h(acc[mt][i][2] + bu0, acc[mt][8 + i][2] + bv0);
            float h11 = gru_h(acc[mt][i][3] + bu1, acc[mt][8 + i][3] + bv1);
            rs0 += h00 + h01; dt0 = fmaf(h00, w0, fmaf(h01, w1, dt0));
            rs1 += h10 + h11; dt1 = fmaf(h10, w0, fmaf(h11, w1, dt1));
        }
#pragma unroll
        for (int s = 1; s < 4; s <<= 1) {
            rs0 += __shfl_xor_sync(0xffffffffu, rs0, s);
            dt0 += __shfl_xor_sync(0xffffffffu, dt0, s);
            rs1 += __shfl_xor_sync(0xffffffffu, rs1, s);
            dt1 += __shfl_xor_sync(0xffffffffu, dt1, s);
        }
        if ((lane & 3) == 0) {
            int r = wm * 32 + mt * 16 + (lane >> 2);
            atomicAdd(&smf[r],           rs0);
            atomicAdd(&smf[128 + r],     dt0);
            atomicAdd(&smf[r + 8],       rs1);
            atomicAdd(&smf[128 + r + 8], dt1);
        }
    }
    __syncthreads();
    if (tid < 128) {
        long grow = rowBase + tid;
        outbuf[grow]      = smf[128 + tid] + bl;   // out = h @ W_lin + b_lin
        outbuf[NN + grow] = sqrtf(smf[tid]);       // logits = sqrt(rowsum(relu(H)))
    }
}

// ---------------- launch orchestration -------------------------------------
extern "C" void kernel_launch(void* const* d_in, const int* in_sizes, int n_in,
                              void* d_out, int out_size) {
    const float* x  = (const float*)d_in[0];
    const void*  ei = d_in[1];                 // int32 or int64 — detected on device
    const float* ew = (const float*)d_in[2];
    const float* Wx = (const float*)d_in[3];
    // d_in[4] = W_h : provably unused (H==0 => cheb(H,*) == bias)
    const float* bx = (const float*)d_in[5];
    const float* bh = (const float*)d_in[6];
    const float* Wl = (const float*)d_in[7];
    const float* bl = (const float*)d_in[8];
    float* out = (float*)d_out;
    (void)in_sizes; (void)n_in; (void)out_size;

    void *pXh, *pY1, *pY2, *pY3, *pdeg, *pcnt, *pany;
    cudaGetSymbolAddress(&pXh, g_xh);
    cudaGetSymbolAddress(&pY1, g_Y1);
    cudaGetSymbolAddress(&pY2, g_Y2);
    cudaGetSymbolAddress(&pY3, g_Y3);
    cudaGetSymbolAddress(&pdeg, g_deg);
    cudaGetSymbolAddress(&pcnt, g_cnt);
    cudaGetSymbolAddress(&pany, g_any);

    cudaFuncSetAttribute(k_gemm_mma, cudaFuncAttributeMaxDynamicSharedMemorySize, SM_DYN);

    // ---- prep
    cudaMemsetAsync(pdeg, 0, (size_t)NN * sizeof(float));
    cudaMemsetAsync(pcnt, 0, (size_t)NN * sizeof(int));
    cudaMemsetAsync(pany, 0, sizeof(int));
    k_detect <<<16, 256>>>((const int*)ei);
    k_setflag<<<1, 1>>>();
    k_xcast  <<<(NN * FI / 4) / 256, 256>>>((const float4*)x);
    k_pack   <<<256, 256>>>(Wx, bx, bh);
    k_deg    <<<NE / 256, 256>>>(ei, ew);
    k_dinv   <<<NN / 256, 256>>>();
    k_scan   <<<1, 1024>>>();
    k_scatter<<<NE / 256, 256>>>(ei, ew);

    // ---- power basis: Y1 = L x ; Y2 = L Y1 ; Y3 = L Y2   (fp16 storage)
    k_spmm<<<NN / 8, 256>>>((const uint2*)pXh, (uint2*)pY1);
    k_spmm<<<NN / 8, 256>>>((const uint2*)pY1, (uint2*)pY2);
    k_spmm<<<NN / 8, 256>>>((const uint2*)pY2, (uint2*)pY3);

    // ---- fused mma.sync GEMM + GRU + head
    k_gemm_mma<<<NN / 128, 256, SM_DYN>>>(Wl, bl, out);
}

// round 8
// speedup vs baseline: 1.5215x; 1.1455x over previous
#include <cuda_runtime.h>
#include <cuda_fp16.h>
#include <cstdint>

#define NN 131072
#define NE 4194304
#define FI 64

// ---------------- scratch (device globals: no allocation allowed) ----------
__device__ float  g_deg [NN];        // degree, then dinv in-place
__device__ int    g_cnt [NN];        // in-degree histogram (by dst)
__device__ int    g_off [NN + 1];    // CSR row offsets (by dst)
__device__ int    g_rank[NE];        // per-edge rank within its dst row
__device__ int2   g_edge[NE];        // CSR record: {src, weight-bits}
__device__ __half g_xh[NN * FI];     // x cast to fp16
__device__ __half g_Y1[NN * FI];     // Y1 = L x
__device__ __half g_Y2[NN * FI];     // Y2 = L Y1
__device__ __half g_Y3[NN * FI];     // Y3 = L Y2
// B operand [chunk kb][n 0..255][k 0..63] fp16, SW128-pre-swizzled (32KB/chunk)
__device__ __half g_B[4 * 256 * 64];
__device__ float  g_bias[256];       // b_x[g]+b_h[g] for gate0|gate2
__device__ int    g_any;             // detector: any odd word nonzero?
__device__ int    g_is64;            // 1 if edge_index is int64

// ---------------- edge-index access (dtype-robust, trap-proof) -------------
__device__ __forceinline__ int eidx(const void* ei, unsigned i) {
    int v;
    if (g_is64) v = (int)((const long long*)ei)[i];
    else        v = ((const int*)ei)[i];
    return v & (NN - 1);             // NN = 2^17: no-op for valid ids, trap-proof
}

// ---------------- helpers ----------------------------------------------------
__device__ __forceinline__ uint32_t smem_u32(const void* p) {
    uint32_t a;
    asm("{ .reg .u64 t; cvta.to.shared.u64 t, %1; cvt.u32.u64 %0, t; }"
        : "=r"(a) : "l"(p));
    return a;
}
#define SWZ128(o) ((o) ^ (((o) >> 3) & 0x70))

__device__ __forceinline__ void ldsm4(uint32_t& r0, uint32_t& r1, uint32_t& r2,
                                      uint32_t& r3, uint32_t addr) {
    asm volatile("ldmatrix.sync.aligned.m8n8.x4.shared.b16 {%0,%1,%2,%3}, [%4];"
                 : "=r"(r0), "=r"(r1), "=r"(r2), "=r"(r3) : "r"(addr));
}
__device__ __forceinline__ void mma16816(float* c, const uint32_t* a,
                                         uint32_t b0, uint32_t b1) {
    asm volatile("mma.sync.aligned.m16n8k16.row.col.f32.f16.f16.f32 "
                 "{%0,%1,%2,%3}, {%4,%5,%6,%7}, {%8,%9}, {%0,%1,%2,%3};"
                 : "+f"(c[0]), "+f"(c[1]), "+f"(c[2]), "+f"(c[3])
                 : "r"(a[0]), "r"(a[1]), "r"(a[2]), "r"(a[3]), "r"(b0), "r"(b1));
}
__device__ __forceinline__ void cpa16(uint32_t dst, const void* src) {
    asm volatile("cp.async.cg.shared.global [%0], [%1], 16;"
                 :: "r"(dst), "l"(src));
}
__device__ __forceinline__ float gru_h(float u, float v) {
    float z  = __fdividef(1.f, 1.f + __expf(-u));             // sigmoid
    float th = 1.f - __fdividef(2.f, __expf(2.f * v) + 1.f);  // tanh, inf-safe
    return fmaxf((1.f - z) * th, 0.f);                        // relu((1-z)*tanh)
}

// ---------------- prep kernels ---------------------------------------------
// sample odd 32-bit words of the first 2*NE words: all-zero <=> int64 layout
__global__ void k_detect(const int* __restrict__ w) {
    int t = blockIdx.x * 256 + threadIdx.x;      // 4096 samples
    int stride = (2 * (NE / 4096));
    int v = w[(unsigned)(t * stride + 1)];
    if (__syncthreads_or(v != 0) && threadIdx.x == 0) atomicOr(&g_any, 1);
}
__global__ void k_setflag() { g_is64 = (g_any == 0); }

// x -> fp16 cast
__global__ void k_xcast(const float4* __restrict__ x) {
    int i = blockIdx.x * 256 + threadIdx.x;      // NN*FI/4 threads
    float4 v = x[i];
    __half2 a = __floats2half2_rn(v.x, v.y);
    __half2 b = __floats2half2_rn(v.z, v.w);
    uint2 o;
    o.x = *reinterpret_cast<uint32_t*>(&a);
    o.y = *reinterpret_cast<uint32_t*>(&b);
    *reinterpret_cast<uint2*>(g_xh + (size_t)i * 4) = o;
}

// weighted degree (by src) + in-degree histogram (by dst); histogram atomic's
// return value IS the CSR rank -> saved for atomic-free scatter
__global__ void k_deg(const void* __restrict__ ei, const float* __restrict__ ew) {
    unsigned e = blockIdx.x * 256 + threadIdx.x;
    if (e >= NE) return;
    atomicAdd(&g_deg[eidx(ei, e)], ew[e]);
    g_rank[e] = atomicAdd(&g_cnt[eidx(ei, NE + e)], 1);
}

__global__ void k_dinv() {
    int i = blockIdx.x * 256 + threadIdx.x;
    if (i < NN) {
        float d = g_deg[i];
        g_deg[i] = (d > 0.f) ? rsqrtf(d) : 0.f;
    }
}

// single-block exclusive scan of g_cnt -> g_off  (1024 threads)
__global__ void k_scan() {
    __shared__ int wsum[32];
    __shared__ int carry_s;
    const int tid  = threadIdx.x;
    const int lane = tid & 31;
    const int w    = tid >> 5;
    int carry = 0;
    for (int base = 0; base < NN; base += 1024) {
        int v = g_cnt[base + tid];
        int x = v;
#pragma unroll
        for (int d = 1; d < 32; d <<= 1) {
            int y = __shfl_up_sync(0xffffffffu, x, d);
            if (lane >= d) x += y;
        }
        if (lane == 31) wsum[w] = x;
        __syncthreads();
        if (w == 0) {
            int s = wsum[lane];
#pragma unroll
            for (int d = 1; d < 32; d <<= 1) {
                int y = __shfl_up_sync(0xffffffffu, s, d);
                if (lane >= d) s += y;
            }
            wsum[lane] = s;
        }
        __syncthreads();
        int incl = x + (w > 0 ? wsum[w - 1] : 0) + carry;
        g_off[base + tid] = incl - v;
        if (tid == 1023) carry_s = incl;
        __syncthreads();
        carry = carry_s;
        __syncthreads();
    }
    if (tid == 0) g_off[NN] = carry;
}

// scatter edges into packed CSR records — NO atomics (rank precomputed)
__global__ void k_scatter(const void* __restrict__ ei, const float* __restrict__ ew) {
    unsigned e = blockIdx.x * 256 + threadIdx.x;
    if (e >= NE) return;
    int s = eidx(ei, e);
    int d = eidx(ei, NE + e);
    float w = -g_deg[s] * ew[e] * g_deg[d];
    unsigned pos = (unsigned)(g_off[d] + g_rank[e]) & (NE - 1);  // trap-proof
    g_edge[pos] = make_int2(s, __float_as_int(w));
}

// Pack B: reparametrized Chebyshev weights (Y_k = L^k x basis), transposed
// [n][k], fp16, SW128-pre-swizzled.
//   B0 = W0 - W2 ; B1 = W1 - 3*W3 ; B2 = 2*W2 ; B3 = 4*W3
__global__ void k_pack(const float* __restrict__ Wx, const float* __restrict__ bx,
                       const float* __restrict__ bh) {
    int i = blockIdx.x * 256 + threadIdx.x;   // 65536 total
    int kb = i >> 14, n = (i >> 6) & 255, kk = i & 63;
    int g  = (n < 128) ? 0 : 2;
    int jj = n & 127;
    const size_t base = (size_t)g * 4 * 64 * 128 + (size_t)kk * 128 + jj;
    const size_t kstep = (size_t)64 * 128;
    float w;
    if      (kb == 0) w = Wx[base]             - Wx[base + 2 * kstep];
    else if (kb == 1) w = Wx[base + kstep]     - 3.f * Wx[base + 3 * kstep];
    else if (kb == 2) w = 2.f * Wx[base + 2 * kstep];
    else              w = 4.f * Wx[base + 3 * kstep];
    uint32_t off = SWZ128((uint32_t)(n * 128 + kk * 2));   // byte off in 32KB tile
    g_B[(uint32_t)kb * 16384 + (off >> 1)] = __float2half(w);
    if (kb == 0 && kk == 0) g_bias[n] = bx[g * 128 + jj] + bh[g * 128 + jj];
}

// ---------------- SpMM gather (fp16 rows): out[d] = sum_e w_e * vin[src_e] --
__global__ void __launch_bounds__(256)
k_spmm(const uint2* __restrict__ vin, uint2* __restrict__ vout) {
    const int node = blockIdx.x * 8 + (threadIdx.x >> 5);
    const int lane = threadIdx.x & 31;
    const int lh   = lane & 15;
    const int half = lane >> 4;
    const int beg = g_off[node];
    const int end = g_off[node + 1];

    float4 acc = make_float4(0.f, 0.f, 0.f, 0.f);
    int i = beg + half;
    for (; i + 2 < end; i += 4) {
        int2 e0 = g_edge[i];
        int2 e1 = g_edge[i + 2];
        uint2 u0 = vin[(long)e0.x * 16 + lh];
        uint2 u1 = vin[(long)e1.x * 16 + lh];
        float w0 = __int_as_float(e0.y);
        float w1 = __int_as_float(e1.y);
        float2 f0 = __half22float2(*reinterpret_cast<__half2*>(&u0.x));
        float2 f1 = __half22float2(*reinterpret_cast<__half2*>(&u0.y));
        float2 f2 = __half22float2(*reinterpret_cast<__half2*>(&u1.x));
        float2 f3 = __half22float2(*reinterpret_cast<__half2*>(&u1.y));
        acc.x = fmaf(w0, f0.x, acc.x); acc.y = fmaf(w0, f0.y, acc.y);
        acc.z = fmaf(w0, f1.x, acc.z); acc.w = fmaf(w0, f1.y, acc.w);
        acc.x = fmaf(w1, f2.x, acc.x); acc.y = fmaf(w1, f2.y, acc.y);
        acc.z = fmaf(w1, f3.x, acc.z); acc.w = fmaf(w1, f3.y, acc.w);
    }
    if (i < end) {
        int2 e0 = g_edge[i];
        uint2 u0 = vin[(long)e0.x * 16 + lh];
        float w0 = __int_as_float(e0.y);
        float2 f0 = __half22float2(*reinterpret_cast<__half2*>(&u0.x));
        float2 f1 = __half22float2(*reinterpret_cast<__half2*>(&u0.y));
        acc.x = fmaf(w0, f0.x, acc.x); acc.y = fmaf(w0, f0.y, acc.y);
        acc.z = fmaf(w0, f1.x, acc.z); acc.w = fmaf(w0, f1.y, acc.w);
    }
    acc.x += __shfl_xor_sync(0xffffffffu, acc.x, 16);
    acc.y += __shfl_xor_sync(0xffffffffu, acc.y, 16);
    acc.z += __shfl_xor_sync(0xffffffffu, acc.z, 16);
    acc.w += __shfl_xor_sync(0xffffffffu, acc.w, 16);

    if (half == 0) {
        __half2 h01 = __floats2half2_rn(acc.x, acc.y);
        __half2 h23 = __floats2half2_rn(acc.z, acc.w);
        uint2 o;
        o.x = *reinterpret_cast<uint32_t*>(&h01);
        o.y = *reinterpret_cast<uint32_t*>(&h23);
        vout[(long)node * 16 + lh] = o;
    }
}

// ---------------- mma.sync GEMM [128 rows/CTA, N=256, K=256] + GRU epilogue -
// A fp16 (as stored), B fp16 single; fp32 accum. cp.async double-buffered.
// SMEM (dynamic): [0..1024) row-reduce; A ping-pong @1024 (2x16KB);
//                 B ping-pong @33792 (2x32KB). Total 99328 B.
#define SM_A0  1024
#define SM_B0  33792
#define SM_DYN 99328

__global__ void __launch_bounds__(256, 1)
k_gemm_mma(const float* __restrict__ Wlin, const float* __restrict__ blin,
           float* __restrict__ outbuf) {
    extern __shared__ char smem[];
    float* smf = (float*)smem;               // [0..128) rs, [128..256) dt
    const uint32_t sb  = smem_u32(smem);
    const int tid  = threadIdx.x;
    const int wid  = tid >> 5;
    const int lane = tid & 31;
    const int wm   = wid & 3;                // m quarter: rows wm*32..+31
    const int wn   = wid >> 2;               // n half pattern
    const long rowBase = (long)blockIdx.x * 128;

    if (tid < 128) { smf[tid] = 0.f; smf[128 + tid] = 0.f; }

    const __half* bases[4] = { g_xh + rowBase * FI, g_Y1 + rowBase * FI,
                               g_Y2 + rowBase * FI, g_Y3 + rowBase * FI };

    // async stage of chunk c into buffer b (A swizzled on the fly, B pre-swizzled)
    auto stage = [&](int c, int b) {
        const uint4* Asrc = (const uint4*)bases[c];
        uint32_t abase = sb + SM_A0 + (uint32_t)b * 16384;
#pragma unroll
        for (int it = 0; it < 4; it++) {
            int idx = tid + it * 256;           // 1024 uint4
            int r  = idx >> 3;
            int c8 = idx & 7;
            cpa16(abase + (uint32_t)(r * 128 + ((c8 ^ (r & 7)) << 4)), Asrc + idx);
        }
        const uint4* Bsrc = (const uint4*)(g_B + (size_t)c * 16384);
        uint32_t bbase = sb + SM_B0 + (uint32_t)b * 32768;
#pragma unroll
        for (int it = 0; it < 8; it++) {
            int idx = tid + it * 256;           // 2048 uint4
            cpa16(bbase + (uint32_t)idx * 16, Bsrc + idx);
        }
        asm volatile("cp.async.commit_group;");
    };

    float acc[2][16][4];
#pragma unroll
    for (int mt = 0; mt < 2; mt++)
#pragma unroll
        for (int t = 0; t < 16; t++)
#pragma unroll
            for (int q = 0; q < 4; q++) acc[mt][t][q] = 0.f;

    stage(0, 0);

#pragma unroll 1
    for (int c = 0; c < 4; c++) {
        const int cur = c & 1;
        if (c < 3) {
            stage(c + 1, cur ^ 1);
            asm volatile("cp.async.wait_group 1;");
        } else {
            asm volatile("cp.async.wait_group 0;");
        }
        __syncthreads();

        const uint32_t Aoff = SM_A0 + (uint32_t)cur * 16384;
        const uint32_t Boff = SM_B0 + (uint32_t)cur * 32768;
#pragma unroll
        for (int ks = 0; ks < 4; ks++) {
            uint32_t a[2][4];
#pragma unroll
            for (int mt = 0; mt < 2; mt++) {
                int r = wm * 32 + mt * 16 + (lane & 15);
                int g = 2 * ks + (lane >> 4);
                uint32_t ad = sb + Aoff + (uint32_t)(r * 128 + ((g ^ (r & 7)) << 4));
                ldsm4(a[mt][0], a[mt][1], a[mt][2], a[mt][3], ad);
            }
#pragma unroll
            for (int p = 0; p < 8; p++) {
                int tix = (p < 4) ? (2 * p) : (8 + 2 * (p - 4));
                int ntb = wn * 8 + ((p < 4) ? (2 * p) : (16 + 2 * (p - 4)));
                int n = ntb * 8 + (lane & 7) + ((lane >> 4) << 3);
                int g = 2 * ks + ((lane >> 3) & 1);
                uint32_t bd = sb + Boff + (uint32_t)(n * 128 + ((g ^ (n & 7)) << 4));
                uint32_t b0, b1, b2, b3;
                ldsm4(b0, b1, b2, b3, bd);
                mma16816(acc[0][tix],     a[0], b0, b1);
                mma16816(acc[1][tix],     a[1], b0, b1);
                mma16816(acc[0][tix + 1], a[0], b2, b3);
                mma16816(acc[1][tix + 1], a[1], b2, b3);
            }
        }
        __syncthreads();
    }

    // ---- GRU epilogue on register accumulators -----------------------------
    const float bl = __ldg(blin);
#pragma unroll
    for (int mt = 0; mt < 2; mt++) {
        float rs0 = 0.f, dt0 = 0.f, rs1 = 0.f, dt1 = 0.f;
#pragma unroll
        for (int i = 0; i < 8; i++) {
            int j0 = wn * 64 + i * 8 + 2 * (lane & 3);
            float bu0 = __ldg(g_bias + j0),       bu1 = __ldg(g_bias + j0 + 1);
            float bv0 = __ldg(g_bias + j0 + 128), bv1 = __ldg(g_bias + j0 + 129);
            float w0  = __ldg(Wlin + j0),         w1  = __ldg(Wlin + j0 + 1);
            float h00 = gru_h(acc[mt][i][0] + bu0, acc[mt][8 + i][0] + bv0);
            float h01 = gru_h(acc[mt][i][1] + bu1, acc[mt][8 + i][1] + bv1);
            float h10 = gru_h(acc[mt][i][2] + bu0, acc[mt][8 + i][2] + bv0);
            float h11 = gru_h(acc[mt][i][3] + bu1, acc[mt][8 + i][3] + bv1);
            rs0 += h00 + h01; dt0 = fmaf(h00, w0, fmaf(h01, w1, dt0));
            rs1 += h10 + h11; dt1 = fmaf(h10, w0, fmaf(h11, w1, dt1));
        }
#pragma unroll
        for (int s = 1; s < 4; s <<= 1) {
            rs0 += __shfl_xor_sync(0xffffffffu, rs0, s);
            dt0 += __shfl_xor_sync(0xffffffffu, dt0, s);
            rs1 += __shfl_xor_sync(0xffffffffu, rs1, s);
            dt1 += __shfl_xor_sync(0xffffffffu, dt1, s);
        }
        if ((lane & 3) == 0) {
            int r = wm * 32 + mt * 16 + (lane >> 2);
            atomicAdd(&smf[r],           rs0);
            atomicAdd(&smf[128 + r],     dt0);
            atomicAdd(&smf[r + 8],       rs1);
            atomicAdd(&smf[128 + r + 8], dt1);
        }
    }
    __syncthreads();
    if (tid < 128) {
        long grow = rowBase + tid;
        outbuf[grow]      = smf[128 + tid] + bl;   // out = h @ W_lin + b_lin
        outbuf[NN + grow] = sqrtf(smf[tid]);       // logits = sqrt(rowsum(relu(H)))
    }
}

// ---------------- launch orchestration -------------------------------------
extern "C" void kernel_launch(void* const* d_in, const int* in_sizes, int n_in,
                              void* d_out, int out_size) {
    const float* x  = (const float*)d_in[0];
    const void*  ei = d_in[1];                 // int32 or int64 — detected on device
    const float* ew = (const float*)d_in[2];
    const float* Wx = (const float*)d_in[3];
    // d_in[4] = W_h : provably unused (H==0 => cheb(H,*) == bias)
    const float* bx = (const float*)d_in[5];
    const float* bh = (const float*)d_in[6];
    const float* Wl = (const float*)d_in[7];
    const float* bl = (const float*)d_in[8];
    float* out = (float*)d_out;
    (void)in_sizes; (void)n_in; (void)out_size;

    void *pXh, *pY1, *pY2, *pY3, *pdeg, *pcnt, *pany;
    cudaGetSymbolAddress(&pXh, g_xh);
    cudaGetSymbolAddress(&pY1, g_Y1);
    cudaGetSymbolAddress(&pY2, g_Y2);
    cudaGetSymbolAddress(&pY3, g_Y3);
    cudaGetSymbolAddress(&pdeg, g_deg);
    cudaGetSymbolAddress(&pcnt, g_cnt);
    cudaGetSymbolAddress(&pany, g_any);

    cudaFuncSetAttribute(k_gemm_mma, cudaFuncAttributeMaxDynamicSharedMemorySize, SM_DYN);

    // ---- prep
    cudaMemsetAsync(pdeg, 0, (size_t)NN * sizeof(float));
    cudaMemsetAsync(pcnt, 0, (size_t)NN * sizeof(int));
    cudaMemsetAsync(pany, 0, sizeof(int));
    k_detect <<<16, 256>>>((const int*)ei);
    k_setflag<<<1, 1>>>();
    k_xcast  <<<(NN * FI / 4) / 256, 256>>>((const float4*)x);
    k_pack   <<<256, 256>>>(Wx, bx, bh);
    k_deg    <<<NE / 256, 256>>>(ei, ew);
    k_dinv   <<<NN / 256, 256>>>();
    k_scan   <<<1, 1024>>>();
    k_scatter<<<NE / 256, 256>>>(ei, ew);

    // ---- power basis: Y1 = L x ; Y2 = L Y1 ; Y3 = L Y2   (fp16 storage)
    k_spmm<<<NN / 8, 256>>>((const uint2*)pXh, (uint2*)pY1);
    k_spmm<<<NN / 8, 256>>>((const uint2*)pY1, (uint2*)pY2);
    k_spmm<<<NN / 8, 256>>>((const uint2*)pY2, (uint2*)pY3);

    // ---- fused mma.sync GEMM + GRU + head
    k_gemm_mma<<<NN / 128, 256, SM_DYN>>>(Wl, bl, out);
}